// round 17
// baseline (speedup 1.0000x reference)
#include <cuda_runtime.h>
#include <math.h>

// Batched EKF — three independent 2x2 filters per segment (exact
// factorization of the 6x6 EKF).  R17 = R16 winner + two exact chain cuts:
//   (a) carry p00s = p00_posterior + Q + R  =>  S = fmaf(DT, p01+m, p00s)
//       directly (removes the S = Pp00+R add from the S->iS recurrence);
//   (b) x_new = z - R*w  (exact: xp + (S-R)*iS*y = z - R*w) -- Pp00 never
//       materialized, x-chain collapses to iS->w->x.
// Grid = 2*nb single-warp blocks: [0,nb) filters A+B (ILP-2), [nb,2nb)
// filter C (linear + angle wrap).  Peeled branch-free prefetch loops,
// lg2 per 4-step group, fused deterministic last-block reduction.

#define THREADS 32

__device__ float4 g_partials4[128];
__device__ int    g_count = 0;

__device__ __forceinline__ float tanh_fast(float x){ float y; asm("tanh.approx.f32 %0, %1;" : "=f"(y) : "f"(x)); return y; }
__device__ __forceinline__ float rcp_fast (float x){ float y; asm("rcp.approx.f32 %0, %1;"  : "=f"(y) : "f"(x)); return y; }
__device__ __forceinline__ float lg2_fast (float x){ float y; asm("lg2.approx.f32 %0, %1;"  : "=f"(y) : "f"(x)); return y; }

__global__ void __launch_bounds__(THREADS) ekf_kernel(
    const float* __restrict__ params,
    const float* __restrict__ cp,
    const float* __restrict__ init_state,
    const float* __restrict__ meas,
    float* __restrict__ out,
    int N, int T, int nbAB)
{
    const float DT    = 1.0f / 120.0f;
    const float GRAV  = 9.81f;
    const float KS    = 100.0f;
    const float WRAP  = 4.71238898038469f;   // 1.5*pi
    const float TWOPI = 6.283185307179586f;
    const float LN2   = 0.6931471805599453f;

    const float fric = fabsf(params[0]);
    const float damp = fabsf(params[1]);
    const float fg    = fric * GRAV;
    const float cF    = 1.0f - DT * damp;
    const float nDTfg = -DT * fg;
    const float DTfgk = DT * fg * KS;
    const float cA    = cF - DTfgk;           // a = cA + DTfgk*th^2
    const float cF2   = cF * cF;

    int bid  = blockIdx.x;
    int lane = threadIdx.x;

    float loss = 0.0f;

    if (bid < nbAB) {
        // ================= A+B role (nonlinear, ILP-2) =================
        const float R0 = expf(cp[0]);
        const float R1 = expf(cp[1]);
        const float Qp = expf(cp[3]);
        const float Qv = expf(cp[4]);
        const float nR0 = -R0, nR2_0 = -R0 * R0, RQs0 = 2.0f * R0 + Qp;
        const float nR1 = -R1, nR2_1 = -R1 * R1, RQs1 = 2.0f * R1 + Qp;

        int n = bid * THREADS + lane;
        if (n < N) {
            float xA = init_state[n*6+0], vA = init_state[n*6+2];
            float xB = init_state[n*6+1], vB = init_state[n*6+3];
            // carried: p00s = p00_post + Qp + R  (S = prior p00 + R directly)
            float pA00s = 0.01f + Qp + R0, pA01 = 0.0f, pA11 = 0.01f;
            float pB00s = 0.01f + Qp + R1, pB01 = 0.0f, pB11 = 0.01f;

            const float*  mp  = meas + (size_t)n * T * 3;
            const float4* mp4 = (const float4*)mp;

            float acc_l2 = 0.0f, acc_m = 0.0f;

#define SUB(x_, v_, p00s_, p01_, p11_, Rc_, nR_, nR2_, RQs_, z_) do {          \
            float th  = tanh_fast(KS * (v_));                                  \
            float xp  = fmaf(DT, (v_), (x_));                                  \
            float vp  = fmaf(cF, (v_), nDTfg * th);                            \
            float a   = fmaf(DTfgk, th * th, cA);                              \
            float m_  = fmaf(DT, (p11_), (p01_));                              \
            float Pp01 = a * m_;                                               \
            float S   = fmaf(DT, (p01_) + m_, (p00s_));                        \
            float Pp11 = fmaf(a * a, (p11_), Qv);                              \
            float y  = (z_) - xp;                                              \
            float iS = rcp_fast(S);                                            \
            float w_ = iS * y;                                                 \
            x_ = fmaf((nR_), w_, (z_));                                        \
            v_ = fmaf(Pp01, w_, vp);                                           \
            p00s_ = fmaf((nR2_), iS, (RQs_));                                  \
            p01_  = Pp01 * ((Rc_) * iS);                                       \
            p11_  = fmaf(-(Pp01 * iS), Pp01, Pp11);                            \
            acc_m = fmaf(y, w_, acc_m);                                        \
            sp *= S;                                                           \
        } while (0)

#define STEP2(z0_, z1_) do {                                                   \
            SUB(xA, vA, pA00s, pA01, pA11, R0, nR0, nR2_0, RQs0, (z0_));       \
            SUB(xB, vB, pB00s, pB01, pB11, R1, nR1, nR2_1, RQs1, (z1_));       \
        } while (0)

#define GROUP4(c0_, c1_, c2_) do {                                             \
            float sp = 1.0f;                                                   \
            STEP2((c0_).x, (c0_).y);                                           \
            STEP2((c0_).w, (c1_).x);                                           \
            STEP2((c1_).z, (c1_).w);                                           \
            STEP2((c2_).y, (c2_).z);                                           \
            acc_l2 += lg2_fast(sp);                                            \
        } while (0)

            if ((T & 3) == 0 && (T >> 2) >= 2) {
                int G = T >> 2;
                float4 c0 = mp4[0], c1 = mp4[1], c2 = mp4[2];
                for (int g = 0; g < G - 1; g++) {           // branch-free body
                    int b = (g + 1) * 3;
                    float4 d0 = mp4[b], d1 = mp4[b+1], d2 = mp4[b+2];
                    GROUP4(c0, c1, c2);
                    c0 = d0; c1 = d1; c2 = d2;
                }
                GROUP4(c0, c1, c2);                          // peeled last group
            } else {
                for (int t = 0; t < T; t++) {
                    float sp = 1.0f;
                    STEP2(mp[t*3+0], mp[t*3+1]);
                    acc_l2 += lg2_fast(sp);
                }
            }
#undef GROUP4
#undef STEP2
#undef SUB
            loss = 0.5f * fmaf(LN2, acc_l2, acc_m);
        }
    } else {
        // ================= C role (linear, angle wrap) =================
        const float R2v = expf(cp[2]);
        const float Qt  = expf(cp[5]);
        const float Qo  = expf(cp[6]);
        const float nRc = -R2v, nR2c = -R2v * R2v, RQsc = 2.0f * R2v + Qt;

        int n = (bid - nbAB) * THREADS + lane;
        if (n < N) {
            float xC = init_state[n*6+4], vC = init_state[n*6+5];
            float pC00s = 0.01f + Qt + R2v, pC01 = 0.0f, pC11 = 0.01f;

            const float* mp = meas + (size_t)n * T * 3 + 2;   // z2 stream

            float acc_l2 = 0.0f, acc_m = 0.0f;

// NOTE: for C the innovation is wrapped, so x_new = xp + y_wrapped - R*w
//       (cannot use z directly when wrap fires).  xq = xp + y_wrapped.
#define SUBC(z_) do {                                                          \
            float xp  = fmaf(DT, vC, xC);                                      \
            float vp  = cF * vC;                                               \
            float m_  = fmaf(DT, pC11, pC01);                                  \
            float Pp01 = cF * m_;                                              \
            float S   = fmaf(DT, pC01 + m_, pC00s);                            \
            float Pp11 = fmaf(cF2, pC11, Qo);                                  \
            float y = (z_) - xp;                                               \
            if      (y >  WRAP) y -= TWOPI;                                    \
            else if (y < -WRAP) y += TWOPI;                                    \
            float iS = rcp_fast(S);                                            \
            float w_ = iS * y;                                                 \
            xC = fmaf(nRc, w_, xp + y);                                        \
            vC = fmaf(Pp01, w_, vp);                                           \
            pC00s = fmaf(nR2c, iS, RQsc);                                      \
            pC01  = Pp01 * (R2v * iS);                                         \
            pC11  = fmaf(-(Pp01 * iS), Pp01, Pp11);                            \
            acc_m = fmaf(y, w_, acc_m);                                        \
            sp *= S;                                                           \
        } while (0)

#define CGROUP4(z0_, z1_, z2_, z3_) do {                                       \
            float sp = 1.0f;                                                   \
            SUBC(z0_); SUBC(z1_); SUBC(z2_); SUBC(z3_);                        \
            acc_l2 += lg2_fast(sp);                                            \
        } while (0)

            if ((T & 3) == 0 && (T >> 2) >= 2) {
                int G = T >> 2;
                float z0 = mp[0], z1 = mp[3], z2 = mp[6], z3 = mp[9];
                for (int g = 0; g < G - 1; g++) {           // branch-free body
                    const float* q = mp + (g + 1) * 12;
                    float n0 = q[0], n1 = q[3], n2 = q[6], n3 = q[9];
                    CGROUP4(z0, z1, z2, z3);
                    z0 = n0; z1 = n1; z2 = n2; z3 = n3;
                }
                CGROUP4(z0, z1, z2, z3);                     // peeled last group
            } else {
                for (int t = 0; t < T; t++) {
                    float sp = 1.0f;
                    SUBC(mp[t*3]);
                    acc_l2 += lg2_fast(sp);
                }
            }
#undef CGROUP4
#undef SUBC
            loss = 0.5f * fmaf(LN2, acc_l2, acc_m);
        }
    }

    // ---- deterministic warp-tree reduction + last-block finish ----
    #pragma unroll
    for (int o = 16; o > 0; o >>= 1)
        loss += __shfl_down_sync(0xffffffffu, loss, o);

    int nbt = gridDim.x;
    int last = 0;
    if (lane == 0) {
        __stwt(&((float*)g_partials4)[bid], loss);
        __threadfence();
        int old = atomicAdd(&g_count, 1);
        last = (old == nbt - 1);
    }
    last = __shfl_sync(0xffffffffu, last, 0);
    if (last) {
        __threadfence();
        float s = 0.0f;
        if ((nbt & 127) == 0) {
            int nq = nbt >> 2;
            for (int j = lane; j < nq; j += 32) {
                float4 v = g_partials4[j];
                s += (v.x + v.y) + (v.z + v.w);
            }
        } else {
            const float* gp = (const float*)g_partials4;
            for (int j = lane; j < nbt; j += 32) s += gp[j];
        }
        #pragma unroll
        for (int o = 16; o > 0; o >>= 1)
            s += __shfl_down_sync(0xffffffffu, s, o);
        if (lane == 0) {
            out[0] = s / (float)N;
            g_count = 0;   // reset for next graph replay
        }
    }
}

extern "C" void kernel_launch(void* const* d_in, const int* in_sizes, int n_in,
                              void* d_out, int out_size)
{
    const float* params = (const float*)d_in[0];
    const float* cp     = (const float*)d_in[1];
    const float* x0     = (const float*)d_in[2];
    const float* meas   = (const float*)d_in[3];
    float* out = (float*)d_out;

    int N = in_sizes[2] / 6;
    int T = in_sizes[3] / (N * 3);
    int nbAB = (N + THREADS - 1) / THREADS;

    ekf_kernel<<<2 * nbAB, THREADS>>>(params, cp, x0, meas, out, N, T, nbAB);
}